// round 8
// baseline (speedup 1.0000x reference)
#include <cuda_runtime.h>
#include <cuda_bf16.h>
#include <math.h>
#include <stdint.h>

#define NUM_CLASSES 13
#define C1 14                        // NUM_CLASSES+1
#define ROWS 1600000                 // 32*1000*50
#define TPB 256
#define TPT 5                        // logit tiles per block
#define NBUF 3
#define GRID (ROWS / (TPB * TPT))    // 1250
#define TILE_BYTES (TPB * C1 * 4)    // 14336
#define DOA4_BLK (TPB * TPT * 3 / 4) // 960 float4 per block per doa array
#define W_CLASS 1.0
#define W_DOA   2.0

__device__ double g_acc[3];
__device__ unsigned int g_ticket;

__device__ __forceinline__ unsigned int smem_u32(const void* p) {
    return (unsigned int)__cvta_generic_to_shared(p);
}
__device__ __forceinline__ void mbar_init(unsigned int bar, unsigned int cnt) {
    asm volatile("mbarrier.init.shared.b64 [%0], %1;" :: "r"(bar), "r"(cnt) : "memory");
}
__device__ __forceinline__ void mbar_expect_tx(unsigned int bar, unsigned int bytes) {
    asm volatile("mbarrier.arrive.expect_tx.shared.b64 _, [%0], %1;" :: "r"(bar), "r"(bytes) : "memory");
}
__device__ __forceinline__ void mbar_wait(unsigned int bar, unsigned int phase) {
    unsigned int done;
    asm volatile(
        "{\n\t.reg .pred p;\n\t"
        "mbarrier.try_wait.parity.acquire.cta.shared::cta.b64 p, [%1], %2;\n\t"
        "selp.b32 %0, 1, 0, p;\n\t}"
        : "=r"(done) : "r"(bar), "r"(phase) : "memory");
    if (!done) {
        asm volatile(
            "{\n\t.reg .pred P1;\n\t"
            "WL_%=:\n\t"
            "mbarrier.try_wait.parity.acquire.cta.shared::cta.b64 P1, [%0], %1, 0x989680;\n\t"
            "@P1 bra.uni WD_%=;\n\t"
            "bra.uni WL_%=;\n\t"
            "WD_%=:\n\t}"
            :: "r"(bar), "r"(phase) : "memory");
    }
}
__device__ __forceinline__ void tma_bulk_1d(unsigned int dst, const void* src,
                                            unsigned int bytes, unsigned int bar) {
    asm volatile(
        "cp.async.bulk.shared::cta.global.mbarrier::complete_tx::bytes [%0], [%1], %2, [%3];"
        :: "r"(dst), "l"(src), "r"(bytes), "r"(bar) : "memory");
}

__global__ __launch_bounds__(TPB, 5)
void loss_fused_kernel(const float* __restrict__ pred_logits,
                       const float* __restrict__ pred_doa,
                       const float* __restrict__ target_doa,
                       const float* __restrict__ empty_weight,
                       const int*   __restrict__ target_classes,
                       float* __restrict__ out) {
    __shared__ __align__(16) float s_log[NBUF][TPB * C1];   // 3 x 14336 B
    __shared__ __align__(8)  unsigned long long s_mbar[NBUF];
    __shared__ float s_ew[C1];
    __shared__ float r_ce[8], r_ab[8], r_ct[8];
    __shared__ bool  s_last;

    const int tid = threadIdx.x;
    const int base = blockIdx.x * TPT;

    if (tid < C1) s_ew[tid] = empty_weight[tid];

    // ---- mbarrier init (fresh smem each launch; graph-safe) ----
    if (tid == 0) {
        #pragma unroll
        for (int b = 0; b < NBUF; b++) mbar_init(smem_u32(&s_mbar[b]), 1);
        asm volatile("fence.proxy.async.shared::cta;" ::: "memory");
    }
    __syncthreads();

    // ---- TMA issue: one bulk copy per logit tile, single thread ----
    auto issue = [&](int buf, int tile) {
        if (tid == 0) {
            unsigned int bar = smem_u32(&s_mbar[buf]);
            mbar_expect_tx(bar, TILE_BYTES);
            tma_bulk_1d(smem_u32(&s_log[buf][0]),
                        pred_logits + (size_t)tile * TPB * C1,
                        TILE_BYTES, bar);
        }
    };

    // ---- prologue: 3 tiles in flight via TMA ----
    issue(0, base);
    issue(1, base + 1);
    issue(2, base + 2);

    // ---- prefetch all per-thread targets (coalesced LDG.32 x5) ----
    int tgs[TPT];
    #pragma unroll
    for (int k = 0; k < TPT; k++)
        tgs[k] = __ldg(target_classes + (size_t)(base + k) * TPB + tid);

    // ---- DOA phase on the LSU path, overlapped with TMA flight ----
    float acc_ab = 0.0f;
    {
        const float4* pd4 = reinterpret_cast<const float4*>(pred_doa);
        const float4* td4 = reinterpret_cast<const float4*>(target_doa);
        const int f4base = blockIdx.x * DOA4_BLK;
        #pragma unroll
        for (int u = 0; u < 4; u++) {
            int i = u * TPB + tid;
            if (u < 3 || i < DOA4_BLK) {
                int g = f4base + i;
                float4 p = __ldg(pd4 + g);
                float4 t = __ldg(td4 + g);
                int e = g * 4;
                int q0 = e / 3;
                int r  = e - q0 * 3;                 // e % 3
                float m0 = (__ldg(target_classes + q0)     != NUM_CLASSES) ? 1.0f : 0.0f;
                float m1 = (__ldg(target_classes + q0 + 1) != NUM_CLASSES) ? 1.0f : 0.0f;
                float mA = (r + 0 >= 3) ? m1 : m0;
                float mB = (r + 1 >= 3) ? m1 : m0;
                float mC = (r + 2 >= 3) ? m1 : m0;
                float mD = m1;
                acc_ab += mA * fabsf(p.x - t.x) + mB * fabsf(p.y - t.y)
                        + mC * fabsf(p.z - t.z) + mD * fabsf(p.w - t.w);
            }
        }
    }

    // ---- CE phase: 3-deep TMA pipeline ----
    float acc_ce = 0.0f, acc_ct = 0.0f;

    #pragma unroll
    for (int k = 0; k < TPT; k++) {
        const int buf = k % NBUF;
        const unsigned int phase = (unsigned int)(k / NBUF) & 1u;
        const int tg = tgs[k];

        mbar_wait(smem_u32(&s_mbar[buf]), phase);   // tile k landed

        const float2* rp = reinterpret_cast<const float2*>(&s_log[buf][tid * C1]);
        float v[C1];
        #pragma unroll
        for (int j = 0; j < C1 / 2; j++) {
            float2 p = rp[j];
            v[2 * j] = p.x; v[2 * j + 1] = p.y;
        }
        float m = fmaxf(fmaxf(fmaxf(fmaxf(v[0], v[1]), fmaxf(v[2], v[3])),
                              fmaxf(fmaxf(v[4], v[5]), fmaxf(v[6], v[7]))),
                        fmaxf(fmaxf(fmaxf(v[8], v[9]), fmaxf(v[10], v[11])),
                              fmaxf(v[12], v[13])));
        float s = 0.0f;
        #pragma unroll
        for (int j = 0; j < C1; j++) s += __expf(v[j] - m);
        float vt = s_log[buf][tid * C1 + tg];       // single dynamic LDS
        acc_ce += s_ew[tg] * (__logf(s) + m - vt);
        if (tg != NUM_CLASSES) acc_ct += 1.0f;

        if (k + NBUF < TPT) {
            __syncthreads();                        // all threads done reading buf
            issue(buf, base + k + NBUF);
        }
    }

    // ---- block reduction ----
    #pragma unroll
    for (int off = 16; off > 0; off >>= 1) {
        acc_ce += __shfl_down_sync(0xFFFFFFFFu, acc_ce, off);
        acc_ab += __shfl_down_sync(0xFFFFFFFFu, acc_ab, off);
        acc_ct += __shfl_down_sync(0xFFFFFFFFu, acc_ct, off);
    }
    const int lane = tid & 31, wid = tid >> 5;
    if (lane == 0) { r_ce[wid] = acc_ce; r_ab[wid] = acc_ab; r_ct[wid] = acc_ct; }
    __syncthreads();

    if (tid == 0) {
        float tce = 0.0f, tab = 0.0f, tct = 0.0f;
        #pragma unroll
        for (int w = 0; w < 8; w++) { tce += r_ce[w]; tab += r_ab[w]; tct += r_ct[w]; }
        atomicAdd(&g_acc[0], (double)tce);
        atomicAdd(&g_acc[1], (double)tab);
        atomicAdd(&g_acc[2], (double)tct);
        __threadfence();
        unsigned int ticket = atomicAdd(&g_ticket, 1u);
        s_last = (ticket == GRID - 1);
    }
    __syncthreads();

    if (s_last && tid == 0) {
        double ce = g_acc[0], ab = g_acc[1], ct = g_acc[2];
        double loss_class = ce / (double)ROWS;
        double n_elems = ct * 3.0;
        double loss_doa = (n_elems > 0.0) ? (ab / fmax(n_elems, 1.0)) : 0.0;
        out[0] = (float)(W_CLASS * loss_class + W_DOA * loss_doa);
        g_acc[0] = 0.0; g_acc[1] = 0.0; g_acc[2] = 0.0;
        __threadfence();
        g_ticket = 0u;
    }
}

extern "C" void kernel_launch(void* const* d_in, const int* in_sizes, int n_in,
                              void* d_out, int out_size) {
    const float* pred_logits    = (const float*)d_in[0];
    const float* pred_doa       = (const float*)d_in[1];
    const float* target_doa     = (const float*)d_in[2];
    const float* empty_weight   = (const float*)d_in[3];
    const int*   target_classes = (const int*)d_in[4];
    float* out = (float*)d_out;

    loss_fused_kernel<<<GRID, TPB>>>(pred_logits, pred_doa, target_doa,
                                     empty_weight, target_classes, out);
}